// round 1
// baseline (speedup 1.0000x reference)
#include <cuda_runtime.h>
#include <cuda_bf16.h>
#include <math.h>

// ---------------------------------------------------------------------------
// GPT Sparse Transformer Block  (B=2, S=2048, D=1024, H=16, Dh=64, HID=4096)
// Round 1: correct fp32 baseline.
//   LN1 -> QKV gemms -> sparse attention -> Wo gemm (+residual)
//   -> LN2 -> W1 gemm (+GELU) -> W2 gemm (+residual)
// ---------------------------------------------------------------------------

#define D_MODEL 1024
#define N_HEADS 16
#define HEAD_DIM 64
#define HIDDEN 4096
#define SEQ 2048
#define BATCH 2
#define BLK 16
#define M_ROWS (BATCH * SEQ)   // 4096

// ------------------------- scratch (no allocations allowed) ----------------
__device__ float g_h  [M_ROWS * D_MODEL];   // LN output (reused for LN2)
__device__ float g_q  [M_ROWS * D_MODEL];
__device__ float g_k  [M_ROWS * D_MODEL];
__device__ float g_v  [M_ROWS * D_MODEL];
__device__ float g_ctx[M_ROWS * D_MODEL];
__device__ float g_x1 [M_ROWS * D_MODEL];   // after attention residual
__device__ float g_ff [M_ROWS * HIDDEN];    // GELU(h2 @ w1 + b1)

// ------------------------------- LayerNorm ---------------------------------
__global__ void __launch_bounds__(256) ln_kernel(
    const float* __restrict__ x, const float* __restrict__ gg,
    const float* __restrict__ bb, float* __restrict__ out)
{
    __shared__ float red[2][8];
    int row = blockIdx.x;
    int tid = threadIdx.x;
    const float4* xr = reinterpret_cast<const float4*>(x + (size_t)row * D_MODEL);
    float4 v = xr[tid];
    float s  = v.x + v.y + v.z + v.w;
    float sq = v.x*v.x + v.y*v.y + v.z*v.z + v.w*v.w;
    #pragma unroll
    for (int o = 16; o; o >>= 1) {
        s  += __shfl_xor_sync(0xFFFFFFFFu, s,  o);
        sq += __shfl_xor_sync(0xFFFFFFFFu, sq, o);
    }
    if ((tid & 31) == 0) { red[0][tid >> 5] = s; red[1][tid >> 5] = sq; }
    __syncthreads();
    if (tid < 32) {
        float a  = (tid < 8) ? red[0][tid] : 0.f;
        float b2 = (tid < 8) ? red[1][tid] : 0.f;
        #pragma unroll
        for (int o = 4; o; o >>= 1) {
            a  += __shfl_xor_sync(0xFFFFFFFFu, a,  o);
            b2 += __shfl_xor_sync(0xFFFFFFFFu, b2, o);
        }
        if (tid == 0) { red[0][0] = a; red[1][0] = b2; }
    }
    __syncthreads();
    float mean = red[0][0] * (1.f / D_MODEL);
    float var  = red[1][0] * (1.f / D_MODEL) - mean * mean;
    float inv  = rsqrtf(var + 1e-5f);
    float4 g4 = reinterpret_cast<const float4*>(gg)[tid];
    float4 b4 = reinterpret_cast<const float4*>(bb)[tid];
    float4 o4;
    o4.x = (v.x - mean) * inv * g4.x + b4.x;
    o4.y = (v.y - mean) * inv * g4.y + b4.y;
    o4.z = (v.z - mean) * inv * g4.z + b4.z;
    o4.w = (v.w - mean) * inv * g4.w + b4.w;
    reinterpret_cast<float4*>(out + (size_t)row * D_MODEL)[tid] = o4;
}

// --------------------------------- SGEMM -----------------------------------
// C[M,N] = A[M,K] @ B[K,N] + bias  (+res / +GELU per EPI)
//   EPI 0: bias only
//   EPI 1: bias + residual (res[M,N])
//   EPI 2: bias + exact GELU
template <int EPI>
__global__ void __launch_bounds__(256) sgemm_kernel(
    const float* __restrict__ A, const float* __restrict__ B,
    const float* __restrict__ bias, const float* __restrict__ res,
    float* __restrict__ C, int M, int N, int K)
{
    constexpr int BM = 128, BN = 128, BK = 16;
    __shared__ float As[BK][BM + 4];
    __shared__ float Bs[BK][BN];

    int tid = threadIdx.x;
    int bm = blockIdx.y * BM;
    int bn = blockIdx.x * BN;

    int tx = tid & 15;        // 0..15 -> col group
    int ty = tid >> 4;        // 0..15 -> row group

    int a_row  = tid >> 2;    // 0..63
    int a_col4 = tid & 3;     // 0..3  -> k offset 4*a_col4
    int b_row  = tid >> 5;    // 0..7
    int b_col4 = tid & 31;    // 0..31 -> n offset 4*b_col4

    float acc[8][8];
    #pragma unroll
    for (int i = 0; i < 8; i++)
        #pragma unroll
        for (int j = 0; j < 8; j++) acc[i][j] = 0.f;

    for (int k0 = 0; k0 < K; k0 += BK) {
        #pragma unroll
        for (int r = 0; r < 2; r++) {
            int row = a_row + r * 64;
            float4 v = *reinterpret_cast<const float4*>(
                &A[(size_t)(bm + row) * K + k0 + a_col4 * 4]);
            As[a_col4 * 4 + 0][row] = v.x;
            As[a_col4 * 4 + 1][row] = v.y;
            As[a_col4 * 4 + 2][row] = v.z;
            As[a_col4 * 4 + 3][row] = v.w;
        }
        #pragma unroll
        for (int r = 0; r < 2; r++) {
            int row = b_row + r * 8;
            *reinterpret_cast<float4*>(&Bs[row][b_col4 * 4]) =
                *reinterpret_cast<const float4*>(
                    &B[(size_t)(k0 + row) * N + bn + b_col4 * 4]);
        }
        __syncthreads();
        #pragma unroll
        for (int kk = 0; kk < BK; kk++) {
            float a[8], b[8];
            float4 a0 = *reinterpret_cast<const float4*>(&As[kk][ty * 8]);
            float4 a1 = *reinterpret_cast<const float4*>(&As[kk][ty * 8 + 4]);
            float4 b0 = *reinterpret_cast<const float4*>(&Bs[kk][tx * 8]);
            float4 b1 = *reinterpret_cast<const float4*>(&Bs[kk][tx * 8 + 4]);
            a[0]=a0.x; a[1]=a0.y; a[2]=a0.z; a[3]=a0.w;
            a[4]=a1.x; a[5]=a1.y; a[6]=a1.z; a[7]=a1.w;
            b[0]=b0.x; b[1]=b0.y; b[2]=b0.z; b[3]=b0.w;
            b[4]=b1.x; b[5]=b1.y; b[6]=b1.z; b[7]=b1.w;
            #pragma unroll
            for (int i = 0; i < 8; i++)
                #pragma unroll
                for (int j = 0; j < 8; j++)
                    acc[i][j] = fmaf(a[i], b[j], acc[i][j]);
        }
        __syncthreads();
    }

    #pragma unroll
    for (int i = 0; i < 8; i++) {
        size_t m = (size_t)(bm + ty * 8 + i);
        #pragma unroll
        for (int j = 0; j < 8; j += 4) {
            int n = bn + tx * 8 + j;
            float4 bv = *reinterpret_cast<const float4*>(&bias[n]);
            float4 r;
            r.x = acc[i][j + 0] + bv.x;
            r.y = acc[i][j + 1] + bv.y;
            r.z = acc[i][j + 2] + bv.z;
            r.w = acc[i][j + 3] + bv.w;
            if (EPI == 1) {
                float4 rv = *reinterpret_cast<const float4*>(&res[m * N + n]);
                r.x += rv.x; r.y += rv.y; r.z += rv.z; r.w += rv.w;
            }
            if (EPI == 2) {
                r.x = 0.5f * r.x * (1.f + erff(r.x * 0.70710678118654752f));
                r.y = 0.5f * r.y * (1.f + erff(r.y * 0.70710678118654752f));
                r.z = 0.5f * r.z * (1.f + erff(r.z * 0.70710678118654752f));
                r.w = 0.5f * r.w * (1.f + erff(r.w * 0.70710678118654752f));
            }
            *reinterpret_cast<float4*>(&C[m * N + n]) = r;
        }
    }
}

// ---------------------------- sparse attention ------------------------------
// Sparse Transformer "fixed" causal pattern, BLK=16:
//   allowed keys for query i:  local  j in [i - i%16, i]    -> (i%16)+1 keys
//                              summary j = 16k+15 < i-i%16  -> i/16 keys
// One warp per (b, h, i). max keys = 16 + 127 = 143.
__global__ void __launch_bounds__(128) sparse_attn_kernel(
    const float* __restrict__ Q, const float* __restrict__ K,
    const float* __restrict__ V, float* __restrict__ O)
{
    __shared__ float q_s[4][64];
    __shared__ float p_s[4][160];

    int w    = threadIdx.x >> 5;
    int lane = threadIdx.x & 31;
    int gw   = blockIdx.x * 4 + w;          // 0 .. B*H*S-1
    int i    = gw & (SEQ - 1);
    int bh   = gw >> 11;                    // SEQ = 2048
    int h    = bh & (N_HEADS - 1);
    int b    = bh >> 4;

    size_t base = ((size_t)(b * SEQ + i) * D_MODEL) + h * HEAD_DIM;
    q_s[w][lane]      = Q[base + lane];
    q_s[w][lane + 32] = Q[base + lane + 32];
    __syncwarp();

    int lb   = i & ~(BLK - 1);
    int nloc = (i & (BLK - 1)) + 1;
    int nsum = i >> 4;
    int nk   = nloc + nsum;

    float sc[5];
    float mymax = -1e30f;
    #pragma unroll
    for (int c = 0; c < 5; c++) {
        int t = lane + c * 32;
        if (t < nk) {
            int j = (t < nloc) ? (lb + t) : (((t - nloc) << 4) + 15);
            const float4* kp = reinterpret_cast<const float4*>(
                K + ((size_t)(b * SEQ + j) * D_MODEL) + h * HEAD_DIM);
            float dot = 0.f;
            #pragma unroll
            for (int d = 0; d < 16; d++) {
                float4 kv = kp[d];
                dot = fmaf(kv.x, q_s[w][d * 4 + 0], dot);
                dot = fmaf(kv.y, q_s[w][d * 4 + 1], dot);
                dot = fmaf(kv.z, q_s[w][d * 4 + 2], dot);
                dot = fmaf(kv.w, q_s[w][d * 4 + 3], dot);
            }
            sc[c] = dot * 0.125f;   // 1/sqrt(64)
            mymax = fmaxf(mymax, sc[c]);
        }
    }
    #pragma unroll
    for (int o = 16; o; o >>= 1)
        mymax = fmaxf(mymax, __shfl_xor_sync(0xFFFFFFFFu, mymax, o));

    float mysum = 0.f;
    #pragma unroll
    for (int c = 0; c < 5; c++) {
        int t = lane + c * 32;
        if (t < nk) { sc[c] = __expf(sc[c] - mymax); mysum += sc[c]; }
    }
    #pragma unroll
    for (int o = 16; o; o >>= 1)
        mysum += __shfl_xor_sync(0xFFFFFFFFu, mysum, o);
    float inv = 1.f / mysum;

    #pragma unroll
    for (int c = 0; c < 5; c++) {
        int t = lane + c * 32;
        if (t < nk) p_s[w][t] = sc[c] * inv;
    }
    __syncwarp();

    float acc0 = 0.f, acc1 = 0.f;
    for (int t = 0; t < nk; t++) {
        int j = (t < nloc) ? (lb + t) : (((t - nloc) << 4) + 15);
        const float* vp = V + ((size_t)(b * SEQ + j) * D_MODEL) + h * HEAD_DIM;
        float p = p_s[w][t];
        acc0 = fmaf(p, vp[lane],      acc0);
        acc1 = fmaf(p, vp[lane + 32], acc1);
    }
    O[base + lane]      = acc0;
    O[base + lane + 32] = acc1;
}

// -------------------------------- launch ------------------------------------
static float* sym_addr(const void* sym) {
    void* p = nullptr;
    cudaGetSymbolAddress(&p, sym);
    return reinterpret_cast<float*>(p);
}

extern "C" void kernel_launch(void* const* d_in, const int* in_sizes, int n_in,
                              void* d_out, int out_size)
{
    const float* x     = (const float*)d_in[0];
    const float* ln1_g = (const float*)d_in[1];
    const float* ln1_b = (const float*)d_in[2];
    const float* wq    = (const float*)d_in[3];
    const float* bq    = (const float*)d_in[4];
    const float* wk    = (const float*)d_in[5];
    const float* bk    = (const float*)d_in[6];
    const float* wv    = (const float*)d_in[7];
    const float* bv    = (const float*)d_in[8];
    const float* wo    = (const float*)d_in[9];
    const float* bo    = (const float*)d_in[10];
    const float* ln2_g = (const float*)d_in[11];
    const float* ln2_b = (const float*)d_in[12];
    const float* w1    = (const float*)d_in[13];
    const float* b1    = (const float*)d_in[14];
    const float* w2    = (const float*)d_in[15];
    const float* b2    = (const float*)d_in[16];
    float* out = (float*)d_out;

    float* p_h   = sym_addr(g_h);
    float* p_q   = sym_addr(g_q);
    float* p_k   = sym_addr(g_k);
    float* p_v   = sym_addr(g_v);
    float* p_ctx = sym_addr(g_ctx);
    float* p_x1  = sym_addr(g_x1);
    float* p_ff  = sym_addr(g_ff);

    const int M = M_ROWS;  // 4096

    // LN1
    ln_kernel<<<M, 256>>>(x, ln1_g, ln1_b, p_h);

    // QKV projections
    dim3 gD(D_MODEL / 128, M / 128);
    sgemm_kernel<0><<<gD, 256>>>(p_h, wq, bq, nullptr, p_q, M, D_MODEL, D_MODEL);
    sgemm_kernel<0><<<gD, 256>>>(p_h, wk, bk, nullptr, p_k, M, D_MODEL, D_MODEL);
    sgemm_kernel<0><<<gD, 256>>>(p_h, wv, bv, nullptr, p_v, M, D_MODEL, D_MODEL);

    // Sparse attention: one warp per (b, h, i)
    sparse_attn_kernel<<<(BATCH * N_HEADS * SEQ) / 4, 128>>>(p_q, p_k, p_v, p_ctx);

    // Output projection + residual
    sgemm_kernel<1><<<gD, 256>>>(p_ctx, wo, bo, x, p_x1, M, D_MODEL, D_MODEL);

    // LN2
    ln_kernel<<<M, 256>>>(p_x1, ln2_g, ln2_b, p_h);

    // FFN
    dim3 gH(HIDDEN / 128, M / 128);
    sgemm_kernel<2><<<gH, 256>>>(p_h, w1, b1, nullptr, p_ff, M, HIDDEN, D_MODEL);
    sgemm_kernel<1><<<gD, 256>>>(p_ff, w2, b2, p_x1, out, M, D_MODEL, HIDDEN);
}

// round 2
// speedup vs baseline: 1.8123x; 1.8123x over previous
#include <cuda_runtime.h>
#include <cuda_bf16.h>
#include <math.h>
#include <stdint.h>

// ---------------------------------------------------------------------------
// GPT Sparse Transformer Block  (B=2, S=2048, D=1024, H=16, Dh=64, HID=4096)
// Round 2: tf32 tensor-core GEMMs (mma.sync.m16n8k8), fp32 everything else.
// ---------------------------------------------------------------------------

#define D_MODEL 1024
#define N_HEADS 16
#define HEAD_DIM 64
#define HIDDEN 4096
#define SEQ 2048
#define BATCH 2
#define BLK 16
#define M_ROWS (BATCH * SEQ)   // 4096

// ------------------------- scratch (no allocations allowed) ----------------
__device__ float g_h  [M_ROWS * D_MODEL];
__device__ float g_q  [M_ROWS * D_MODEL];
__device__ float g_k  [M_ROWS * D_MODEL];
__device__ float g_v  [M_ROWS * D_MODEL];
__device__ float g_ctx[M_ROWS * D_MODEL];
__device__ float g_x1 [M_ROWS * D_MODEL];
__device__ float g_ff [M_ROWS * HIDDEN];

// ------------------------------- helpers -----------------------------------
__device__ __forceinline__ uint32_t f2tf32(float x) {
    uint32_t r;
    asm("cvt.rna.tf32.f32 %0, %1;" : "=r"(r) : "f"(x));
    return r;
}

__device__ __forceinline__ void ldsm_x4(uint32_t* r, uint32_t addr) {
    asm volatile("ldmatrix.sync.aligned.m8n8.x4.shared.b16 {%0,%1,%2,%3}, [%4];"
                 : "=r"(r[0]), "=r"(r[1]), "=r"(r[2]), "=r"(r[3]) : "r"(addr));
}

__device__ __forceinline__ void mma_tf32(float* d, const uint32_t* a,
                                         uint32_t b0, uint32_t b1) {
    asm volatile(
        "mma.sync.aligned.m16n8k8.row.col.f32.tf32.tf32.f32 "
        "{%0,%1,%2,%3}, {%4,%5,%6,%7}, {%8,%9}, {%0,%1,%2,%3};"
        : "+f"(d[0]), "+f"(d[1]), "+f"(d[2]), "+f"(d[3])
        : "r"(a[0]), "r"(a[1]), "r"(a[2]), "r"(a[3]), "r"(b0), "r"(b1));
}

// ------------------------------- LayerNorm ---------------------------------
__global__ void __launch_bounds__(256) ln_kernel(
    const float* __restrict__ x, const float* __restrict__ gg,
    const float* __restrict__ bb, float* __restrict__ out)
{
    __shared__ float red[2][8];
    int row = blockIdx.x;
    int tid = threadIdx.x;
    const float4* xr = reinterpret_cast<const float4*>(x + (size_t)row * D_MODEL);
    float4 v = xr[tid];
    float s  = v.x + v.y + v.z + v.w;
    float sq = v.x*v.x + v.y*v.y + v.z*v.z + v.w*v.w;
    #pragma unroll
    for (int o = 16; o; o >>= 1) {
        s  += __shfl_xor_sync(0xFFFFFFFFu, s,  o);
        sq += __shfl_xor_sync(0xFFFFFFFFu, sq, o);
    }
    if ((tid & 31) == 0) { red[0][tid >> 5] = s; red[1][tid >> 5] = sq; }
    __syncthreads();
    if (tid < 32) {
        float a  = (tid < 8) ? red[0][tid] : 0.f;
        float b2 = (tid < 8) ? red[1][tid] : 0.f;
        #pragma unroll
        for (int o = 4; o; o >>= 1) {
            a  += __shfl_xor_sync(0xFFFFFFFFu, a,  o);
            b2 += __shfl_xor_sync(0xFFFFFFFFu, b2, o);
        }
        if (tid == 0) { red[0][0] = a; red[1][0] = b2; }
    }
    __syncthreads();
    float mean = red[0][0] * (1.f / D_MODEL);
    float var  = red[1][0] * (1.f / D_MODEL) - mean * mean;
    float inv  = rsqrtf(var + 1e-5f);
    float4 g4 = reinterpret_cast<const float4*>(gg)[tid];
    float4 b4 = reinterpret_cast<const float4*>(bb)[tid];
    float4 o4;
    o4.x = (v.x - mean) * inv * g4.x + b4.x;
    o4.y = (v.y - mean) * inv * g4.y + b4.y;
    o4.z = (v.z - mean) * inv * g4.z + b4.z;
    o4.w = (v.w - mean) * inv * g4.w + b4.w;
    reinterpret_cast<float4*>(out + (size_t)row * D_MODEL)[tid] = o4;
}

// --------------------------- tf32 tensor GEMM -------------------------------
// C[M,N] = A[M,K] @ B[K,N] + bias   (EPI 0: bias, 1: bias+res, 2: bias+GELU)
// Block 128x128x32, 4 warps, warp tile m64n64 (4 m16-tiles x 8 n8-tiles).
template <int EPI>
__global__ void __launch_bounds__(128) tgemm_kernel(
    const float* __restrict__ A, const float* __restrict__ B,
    const float* __restrict__ bias, const float* __restrict__ res,
    float* __restrict__ C, int M, int N, int K)
{
    constexpr int BM = 128, BN = 128, BK = 32;
    constexpr int LDA = BK + 4;   // 36 floats: conflict-free STS & LDSM
    __shared__ float As[BM][LDA]; // As[m][k]
    __shared__ float Bs[BN][LDA]; // Bs[n][k]  (B transposed)

    const int tid  = threadIdx.x;
    const int wid  = tid >> 5;
    const int lane = tid & 31;
    const int bm = blockIdx.y * BM;
    const int bn = blockIdx.x * BN;

    const int wm = (wid >> 1) * 64;   // warp m offset in tile
    const int wn = (wid & 1) * 64;    // warp n offset in tile

    // A loader: row = (tid>>3)+16r, k4 = (tid&7)*4   -> coalesced LDG + STS.128
    const int ar = tid >> 3;
    const int ac = (tid & 7) * 4;
    // B loader: k = tid&31 (one k per lane), n = 4*(tid>>5) + 16r
    const int bk = tid & 31;
    const int bnw = (tid >> 5) * 4;

    float acc[4][8][4];
    #pragma unroll
    for (int i = 0; i < 4; i++)
        #pragma unroll
        for (int j = 0; j < 8; j++)
            #pragma unroll
            for (int r = 0; r < 4; r++) acc[i][j][r] = 0.f;

    const uint32_t a_base = (uint32_t)__cvta_generic_to_shared(&As[0][0]);
    const uint32_t b_base = (uint32_t)__cvta_generic_to_shared(&Bs[0][0]);
    const int lr = lane & 15;
    const int lh = lane >> 4;

    for (int k0 = 0; k0 < K; k0 += BK) {
        __syncthreads();
        // ---- load A tile (direct, with tf32 round) ----
        #pragma unroll
        for (int r = 0; r < 8; r++) {
            int row = ar + 16 * r;
            float4 v = *reinterpret_cast<const float4*>(
                &A[(size_t)(bm + row) * K + k0 + ac]);
            uint4 t;
            t.x = f2tf32(v.x); t.y = f2tf32(v.y);
            t.z = f2tf32(v.z); t.w = f2tf32(v.w);
            *reinterpret_cast<uint4*>(&As[row][ac]) = t;
        }
        // ---- load B tile transposed: Bs[n][k] ----
        #pragma unroll
        for (int r = 0; r < 8; r++) {
            int n0 = bnw + 16 * r;
            float4 v = *reinterpret_cast<const float4*>(
                &B[(size_t)(k0 + bk) * N + bn + n0]);
            Bs[n0 + 0][bk] = __uint_as_float(f2tf32(v.x));
            Bs[n0 + 1][bk] = __uint_as_float(f2tf32(v.y));
            Bs[n0 + 2][bk] = __uint_as_float(f2tf32(v.z));
            Bs[n0 + 3][bk] = __uint_as_float(f2tf32(v.w));
        }
        __syncthreads();

        // ---- compute 4 k8 steps ----
        #pragma unroll
        for (int ks = 0; ks < 4; ks++) {
            uint32_t af[4][4], bf[4][4];
            #pragma unroll
            for (int mt = 0; mt < 4; mt++)
                ldsm_x4(af[mt], a_base +
                    ((uint32_t)((wm + mt * 16 + lr) * LDA + ks * 8 + lh * 4) << 2));
            #pragma unroll
            for (int np = 0; np < 4; np++)
                ldsm_x4(bf[np], b_base +
                    ((uint32_t)((wn + np * 16 + lr) * LDA + ks * 8 + lh * 4) << 2));
            #pragma unroll
            for (int mt = 0; mt < 4; mt++) {
                #pragma unroll
                for (int np = 0; np < 4; np++) {
                    mma_tf32(acc[mt][2 * np + 0], af[mt], bf[np][0], bf[np][2]);
                    mma_tf32(acc[mt][2 * np + 1], af[mt], bf[np][1], bf[np][3]);
                }
            }
        }
    }

    // ---- epilogue ----
    const int qr = lane >> 2;          // 0..7
    const int qc = 2 * (lane & 3);     // 0,2,4,6
    #pragma unroll
    for (int mt = 0; mt < 4; mt++) {
        int r0 = bm + wm + mt * 16 + qr;
        #pragma unroll
        for (int nt = 0; nt < 8; nt++) {
            int col = bn + wn + nt * 8 + qc;
            float2 bv = *reinterpret_cast<const float2*>(&bias[col]);
            float v0 = acc[mt][nt][0] + bv.x;
            float v1 = acc[mt][nt][1] + bv.y;
            float v2 = acc[mt][nt][2] + bv.x;
            float v3 = acc[mt][nt][3] + bv.y;
            if (EPI == 1) {
                float2 r0v = *reinterpret_cast<const float2*>(&res[(size_t)r0 * N + col]);
                float2 r1v = *reinterpret_cast<const float2*>(&res[(size_t)(r0 + 8) * N + col]);
                v0 += r0v.x; v1 += r0v.y; v2 += r1v.x; v3 += r1v.y;
            }
            if (EPI == 2) {
                v0 = 0.5f * v0 * (1.f + erff(v0 * 0.70710678118654752f));
                v1 = 0.5f * v1 * (1.f + erff(v1 * 0.70710678118654752f));
                v2 = 0.5f * v2 * (1.f + erff(v2 * 0.70710678118654752f));
                v3 = 0.5f * v3 * (1.f + erff(v3 * 0.70710678118654752f));
            }
            *reinterpret_cast<float2*>(&C[(size_t)r0 * N + col])       = make_float2(v0, v1);
            *reinterpret_cast<float2*>(&C[(size_t)(r0 + 8) * N + col]) = make_float2(v2, v3);
        }
    }
}

// ---------------------------- sparse attention ------------------------------
__global__ void __launch_bounds__(128) sparse_attn_kernel(
    const float* __restrict__ Q, const float* __restrict__ K,
    const float* __restrict__ V, float* __restrict__ O)
{
    __shared__ float q_s[4][64];
    __shared__ float p_s[4][160];

    int w    = threadIdx.x >> 5;
    int lane = threadIdx.x & 31;
    int gw   = blockIdx.x * 4 + w;
    int i    = gw & (SEQ - 1);
    int bh   = gw >> 11;
    int h    = bh & (N_HEADS - 1);
    int b    = bh >> 4;

    size_t base = ((size_t)(b * SEQ + i) * D_MODEL) + h * HEAD_DIM;
    q_s[w][lane]      = Q[base + lane];
    q_s[w][lane + 32] = Q[base + lane + 32];
    __syncwarp();

    int lb   = i & ~(BLK - 1);
    int nloc = (i & (BLK - 1)) + 1;
    int nsum = i >> 4;
    int nk   = nloc + nsum;

    float sc[5];
    float mymax = -1e30f;
    #pragma unroll
    for (int c = 0; c < 5; c++) {
        int t = lane + c * 32;
        if (t < nk) {
            int j = (t < nloc) ? (lb + t) : (((t - nloc) << 4) + 15);
            const float4* kp = reinterpret_cast<const float4*>(
                K + ((size_t)(b * SEQ + j) * D_MODEL) + h * HEAD_DIM);
            float dot = 0.f;
            #pragma unroll
            for (int d = 0; d < 16; d++) {
                float4 kv = kp[d];
                dot = fmaf(kv.x, q_s[w][d * 4 + 0], dot);
                dot = fmaf(kv.y, q_s[w][d * 4 + 1], dot);
                dot = fmaf(kv.z, q_s[w][d * 4 + 2], dot);
                dot = fmaf(kv.w, q_s[w][d * 4 + 3], dot);
            }
            sc[c] = dot * 0.125f;
            mymax = fmaxf(mymax, sc[c]);
        }
    }
    #pragma unroll
    for (int o = 16; o; o >>= 1)
        mymax = fmaxf(mymax, __shfl_xor_sync(0xFFFFFFFFu, mymax, o));

    float mysum = 0.f;
    #pragma unroll
    for (int c = 0; c < 5; c++) {
        int t = lane + c * 32;
        if (t < nk) { sc[c] = __expf(sc[c] - mymax); mysum += sc[c]; }
    }
    #pragma unroll
    for (int o = 16; o; o >>= 1)
        mysum += __shfl_xor_sync(0xFFFFFFFFu, mysum, o);
    float inv = 1.f / mysum;

    #pragma unroll
    for (int c = 0; c < 5; c++) {
        int t = lane + c * 32;
        if (t < nk) p_s[w][t] = sc[c] * inv;
    }
    __syncwarp();

    float acc0 = 0.f, acc1 = 0.f;
    for (int t = 0; t < nk; t++) {
        int j = (t < nloc) ? (lb + t) : (((t - nloc) << 4) + 15);
        const float* vp = V + ((size_t)(b * SEQ + j) * D_MODEL) + h * HEAD_DIM;
        float p = p_s[w][t];
        acc0 = fmaf(p, vp[lane],      acc0);
        acc1 = fmaf(p, vp[lane + 32], acc1);
    }
    O[base + lane]      = acc0;
    O[base + lane + 32] = acc1;
}

// -------------------------------- launch ------------------------------------
static float* sym_addr(const void* sym) {
    void* p = nullptr;
    cudaGetSymbolAddress(&p, sym);
    return reinterpret_cast<float*>(p);
}

extern "C" void kernel_launch(void* const* d_in, const int* in_sizes, int n_in,
                              void* d_out, int out_size)
{
    const float* x     = (const float*)d_in[0];
    const float* ln1_g = (const float*)d_in[1];
    const float* ln1_b = (const float*)d_in[2];
    const float* wq    = (const float*)d_in[3];
    const float* bq    = (const float*)d_in[4];
    const float* wk    = (const float*)d_in[5];
    const float* bk    = (const float*)d_in[6];
    const float* wv    = (const float*)d_in[7];
    const float* bv    = (const float*)d_in[8];
    const float* wo    = (const float*)d_in[9];
    const float* bo    = (const float*)d_in[10];
    const float* ln2_g = (const float*)d_in[11];
    const float* ln2_b = (const float*)d_in[12];
    const float* w1    = (const float*)d_in[13];
    const float* b1    = (const float*)d_in[14];
    const float* w2    = (const float*)d_in[15];
    const float* b2    = (const float*)d_in[16];
    float* out = (float*)d_out;

    float* p_h   = sym_addr(g_h);
    float* p_q   = sym_addr(g_q);
    float* p_k   = sym_addr(g_k);
    float* p_v   = sym_addr(g_v);
    float* p_ctx = sym_addr(g_ctx);
    float* p_x1  = sym_addr(g_x1);
    float* p_ff  = sym_addr(g_ff);

    const int M = M_ROWS;

    ln_kernel<<<M, 256>>>(x, ln1_g, ln1_b, p_h);

    dim3 gD(D_MODEL / 128, M / 128);
    tgemm_kernel<0><<<gD, 128>>>(p_h, wq, bq, nullptr, p_q, M, D_MODEL, D_MODEL);
    tgemm_kernel<0><<<gD, 128>>>(p_h, wk, bk, nullptr, p_k, M, D_MODEL, D_MODEL);
    tgemm_kernel<0><<<gD, 128>>>(p_h, wv, bv, nullptr, p_v, M, D_MODEL, D_MODEL);

    sparse_attn_kernel<<<(BATCH * N_HEADS * SEQ) / 4, 128>>>(p_q, p_k, p_v, p_ctx);

    tgemm_kernel<1><<<gD, 128>>>(p_ctx, wo, bo, x, p_x1, M, D_MODEL, D_MODEL);

    ln_kernel<<<M, 256>>>(p_x1, ln2_g, ln2_b, p_h);

    dim3 gH(HIDDEN / 128, M / 128);
    tgemm_kernel<2><<<gH, 128>>>(p_h, w1, b1, nullptr, p_ff, M, HIDDEN, D_MODEL);
    tgemm_kernel<1><<<gD, 128>>>(p_ff, w2, b2, p_x1, out, M, D_MODEL, HIDDEN);
}

// round 3
// speedup vs baseline: 2.4812x; 1.3691x over previous
#include <cuda_runtime.h>
#include <cuda_bf16.h>
#include <math.h>
#include <stdint.h>

// ---------------------------------------------------------------------------
// GPT Sparse Transformer Block  (B=2, S=2048, D=1024, H=16, Dh=64, HID=4096)
// Round 3: tf32 mma.sync GEMMs with 3-stage cp.async pipeline.
//   All GEMM operands pre-rounded to tf32 (rna) at their producers.
// ---------------------------------------------------------------------------

#define D_MODEL 1024
#define N_HEADS 16
#define HEAD_DIM 64
#define HIDDEN 4096
#define SEQ 2048
#define BATCH 2
#define BLK 16
#define M_ROWS (BATCH * SEQ)   // 4096
#define QKV_LD (3 * D_MODEL)   // 3072

// ------------------------- scratch (no allocations allowed) ----------------
__device__ float g_h   [M_ROWS * D_MODEL];        // LN output (tf32-rounded)
__device__ float g_qkv [M_ROWS * QKV_LD];         // fused q|k|v
__device__ float g_ctx [M_ROWS * D_MODEL];        // attn out (tf32-rounded)
__device__ float g_x1  [M_ROWS * D_MODEL];        // after attn residual
__device__ float g_ff  [M_ROWS * HIDDEN];         // GELU out (tf32-rounded)
// rounded weight copies
__device__ float g_wqkv[D_MODEL * QKV_LD];        // wq|wk|wv rounded
__device__ float g_bqkv[QKV_LD];
__device__ float g_wo_r[D_MODEL * D_MODEL];
__device__ float g_w1_r[D_MODEL * HIDDEN];
__device__ float g_w2_r[HIDDEN * D_MODEL];

// ------------------------------- helpers -----------------------------------
__device__ __forceinline__ uint32_t f2tf32(float x) {
    uint32_t r;
    asm("cvt.rna.tf32.f32 %0, %1;" : "=r"(r) : "f"(x));
    return r;
}
__device__ __forceinline__ float rtf(float x) { return __uint_as_float(f2tf32(x)); }

__device__ __forceinline__ void ldsm_x4(uint32_t* r, uint32_t addr) {
    asm volatile("ldmatrix.sync.aligned.m8n8.x4.shared.b16 {%0,%1,%2,%3}, [%4];"
                 : "=r"(r[0]), "=r"(r[1]), "=r"(r[2]), "=r"(r[3]) : "r"(addr));
}
__device__ __forceinline__ void mma_tf32(float* d, const uint32_t* a,
                                         uint32_t b0, uint32_t b1) {
    asm volatile(
        "mma.sync.aligned.m16n8k8.row.col.f32.tf32.tf32.f32 "
        "{%0,%1,%2,%3}, {%4,%5,%6,%7}, {%8,%9}, {%0,%1,%2,%3};"
        : "+f"(d[0]), "+f"(d[1]), "+f"(d[2]), "+f"(d[3])
        : "r"(a[0]), "r"(a[1]), "r"(a[2]), "r"(a[3]), "r"(b0), "r"(b1));
}
__device__ __forceinline__ void cp16(void* smem, const void* g) {
    uint32_t s = (uint32_t)__cvta_generic_to_shared(smem);
    asm volatile("cp.async.cg.shared.global [%0], [%1], 16;" :: "r"(s), "l"(g));
}
__device__ __forceinline__ void cp_commit() {
    asm volatile("cp.async.commit_group;");
}
__device__ __forceinline__ void cp_wait1() {
    asm volatile("cp.async.wait_group 1;");
}

// --------------------- weight round/pack kernel ------------------------------
// dst[r*dstLd4 + c] = rna(src[r*cols4 + c]); grid = (rows, cols4/256), block 256
__global__ void __launch_bounds__(256) round_pack_kernel(
    const float4* __restrict__ src, float4* __restrict__ dst,
    int cols4, int dstLd4)
{
    int r = blockIdx.x;
    int c = blockIdx.y * 256 + threadIdx.x;
    float4 v = src[(size_t)r * cols4 + c];
    v.x = rtf(v.x); v.y = rtf(v.y); v.z = rtf(v.z); v.w = rtf(v.w);
    dst[(size_t)r * dstLd4 + c] = v;
}

// ------------------------------- LayerNorm ----------------------------------
// Output is tf32-rounded (only ever consumed as GEMM A operand).
__global__ void __launch_bounds__(256) ln_kernel(
    const float* __restrict__ x, const float* __restrict__ gg,
    const float* __restrict__ bb, float* __restrict__ out)
{
    __shared__ float red[2][8];
    int row = blockIdx.x;
    int tid = threadIdx.x;
    const float4* xr = reinterpret_cast<const float4*>(x + (size_t)row * D_MODEL);
    float4 v = xr[tid];
    float s  = v.x + v.y + v.z + v.w;
    float sq = v.x*v.x + v.y*v.y + v.z*v.z + v.w*v.w;
    #pragma unroll
    for (int o = 16; o; o >>= 1) {
        s  += __shfl_xor_sync(0xFFFFFFFFu, s,  o);
        sq += __shfl_xor_sync(0xFFFFFFFFu, sq, o);
    }
    if ((tid & 31) == 0) { red[0][tid >> 5] = s; red[1][tid >> 5] = sq; }
    __syncthreads();
    if (tid < 32) {
        float a  = (tid < 8) ? red[0][tid] : 0.f;
        float b2 = (tid < 8) ? red[1][tid] : 0.f;
        #pragma unroll
        for (int o = 4; o; o >>= 1) {
            a  += __shfl_xor_sync(0xFFFFFFFFu, a,  o);
            b2 += __shfl_xor_sync(0xFFFFFFFFu, b2, o);
        }
        if (tid == 0) { red[0][0] = a; red[1][0] = b2; }
    }
    __syncthreads();
    float mean = red[0][0] * (1.f / D_MODEL);
    float var  = red[1][0] * (1.f / D_MODEL) - mean * mean;
    float inv  = rsqrtf(var + 1e-5f);
    float4 g4 = reinterpret_cast<const float4*>(gg)[tid];
    float4 b4 = reinterpret_cast<const float4*>(bb)[tid];
    float4 o4;
    o4.x = rtf((v.x - mean) * inv * g4.x + b4.x);
    o4.y = rtf((v.y - mean) * inv * g4.y + b4.y);
    o4.z = rtf((v.z - mean) * inv * g4.z + b4.z);
    o4.w = rtf((v.w - mean) * inv * g4.w + b4.w);
    reinterpret_cast<float4*>(out + (size_t)row * D_MODEL)[tid] = o4;
}

// --------------------------- tf32 tensor GEMM v3 -----------------------------
// C[M,N] = A[M,K] @ B[K,N] + bias   (EPI 0: bias, 1: bias+res, 2: bias+GELU->tf32)
// Block 128x128x32, 4 warps m64n64, 3-stage cp.async pipeline.
// A, B must already be tf32-rounded.
template <int EPI>
__global__ void __launch_bounds__(128) tgemm_kernel(
    const float* __restrict__ A, const float* __restrict__ B,
    const float* __restrict__ bias, const float* __restrict__ res,
    float* __restrict__ C, int M, int N, int K)
{
    constexpr int BM = 128, BN = 128, BK = 32, STAGES = 3;
    constexpr int LDA = 36;    // floats; 144B rows (16B aligned), LDSM conflict-free
    constexpr int LDB = 136;   // floats; 544B rows; 136 mod 32 = 8 -> LDS conflict-free
    extern __shared__ float sm[];
    float* As = sm;                          // [STAGES][BM][LDA]
    float* Bs = sm + STAGES * BM * LDA;      // [STAGES][BK][LDB]

    const int tid  = threadIdx.x;
    const int wid  = tid >> 5;
    const int lane = tid & 31;
    const int bm = blockIdx.y * BM;
    const int bn = blockIdx.x * BN;
    const int wm = (wid >> 1) * 64;
    const int wn = (wid & 1) * 64;

    // loader lanes
    const int a_row = tid >> 3;          // 0..15 (+16r)
    const int a_kc  = (tid & 7) * 4;     // k chunk
    const int b_k   = tid >> 2;          // 0..31
    const int b_nc  = (tid & 3) * 4;     // n chunk (+16r)
    const float* Ag = A + (size_t)(bm + a_row) * K + a_kc;
    const float* Bg = B + (size_t)b_k * N + bn + b_nc;

    float acc[4][8][4];
    #pragma unroll
    for (int i = 0; i < 4; i++)
        #pragma unroll
        for (int j = 0; j < 8; j++)
            #pragma unroll
            for (int r = 0; r < 4; r++) acc[i][j][r] = 0.f;

    auto load_stage = [&](int stage, int k0) {
        float* Ad = As + stage * (BM * LDA);
        float* Bd = Bs + stage * (BK * LDB);
        #pragma unroll
        for (int r = 0; r < 8; r++)
            cp16(&Ad[(a_row + 16 * r) * LDA + a_kc], Ag + (size_t)(16 * r) * K + k0);
        #pragma unroll
        for (int r = 0; r < 8; r++)
            cp16(&Bd[b_k * LDB + b_nc + 16 * r], Bg + (size_t)k0 * N + 16 * r);
    };

    const int NIT = K / BK;
    load_stage(0, 0);       cp_commit();
    load_stage(1, BK);      cp_commit();

    const int lr = lane & 15;
    const int lh = lane >> 4;
    const int kq = lane & 3;
    const int nq = lane >> 2;

    for (int it = 0; it < NIT; ++it) {
        cp_wait1();
        __syncthreads();
        if (it + 2 < NIT) load_stage((it + 2) % STAGES, (it + 2) * BK);
        cp_commit();

        const float* Ast = As + (it % STAGES) * (BM * LDA);
        const float* Bst = Bs + (it % STAGES) * (BK * LDB);
        const uint32_t a_base = (uint32_t)__cvta_generic_to_shared(Ast);

        #pragma unroll
        for (int ks = 0; ks < 4; ks++) {
            uint32_t af[4][4];
            #pragma unroll
            for (int mt = 0; mt < 4; mt++)
                ldsm_x4(af[mt], a_base +
                    ((uint32_t)((wm + mt * 16 + lr) * LDA + ks * 8 + lh * 4) << 2));
            uint32_t bf0[8], bf1[8];
            #pragma unroll
            for (int nt = 0; nt < 8; nt++) {
                bf0[nt] = __float_as_uint(Bst[(ks * 8 + kq)     * LDB + wn + nt * 8 + nq]);
                bf1[nt] = __float_as_uint(Bst[(ks * 8 + kq + 4) * LDB + wn + nt * 8 + nq]);
            }
            #pragma unroll
            for (int mt = 0; mt < 4; mt++)
                #pragma unroll
                for (int nt = 0; nt < 8; nt++)
                    mma_tf32(acc[mt][nt], af[mt], bf0[nt], bf1[nt]);
        }
        __syncthreads();
    }

    // ---- epilogue ----
    const int qr = lane >> 2;
    const int qc = 2 * (lane & 3);
    #pragma unroll
    for (int mt = 0; mt < 4; mt++) {
        int r0 = bm + wm + mt * 16 + qr;
        #pragma unroll
        for (int nt = 0; nt < 8; nt++) {
            int col = bn + wn + nt * 8 + qc;
            float2 bv = *reinterpret_cast<const float2*>(&bias[col]);
            float v0 = acc[mt][nt][0] + bv.x;
            float v1 = acc[mt][nt][1] + bv.y;
            float v2 = acc[mt][nt][2] + bv.x;
            float v3 = acc[mt][nt][3] + bv.y;
            if (EPI == 1) {
                float2 r0v = *reinterpret_cast<const float2*>(&res[(size_t)r0 * N + col]);
                float2 r1v = *reinterpret_cast<const float2*>(&res[(size_t)(r0 + 8) * N + col]);
                v0 += r0v.x; v1 += r0v.y; v2 += r1v.x; v3 += r1v.y;
            }
            if (EPI == 2) {
                v0 = rtf(0.5f * v0 * (1.f + erff(v0 * 0.70710678118654752f)));
                v1 = rtf(0.5f * v1 * (1.f + erff(v1 * 0.70710678118654752f)));
                v2 = rtf(0.5f * v2 * (1.f + erff(v2 * 0.70710678118654752f)));
                v3 = rtf(0.5f * v3 * (1.f + erff(v3 * 0.70710678118654752f)));
            }
            *reinterpret_cast<float2*>(&C[(size_t)r0 * N + col])       = make_float2(v0, v1);
            *reinterpret_cast<float2*>(&C[(size_t)(r0 + 8) * N + col]) = make_float2(v2, v3);
        }
    }
}

// ---------------------------- sparse attention ------------------------------
// Reads fused qkv buffer (row stride 3072: q|k|v). Writes tf32-rounded ctx.
__global__ void __launch_bounds__(128) sparse_attn_kernel(
    const float* __restrict__ QKV, float* __restrict__ O)
{
    __shared__ float q_s[4][64];
    __shared__ float p_s[4][160];

    int w    = threadIdx.x >> 5;
    int lane = threadIdx.x & 31;
    int gw   = blockIdx.x * 4 + w;
    int i    = gw & (SEQ - 1);
    int bh   = gw >> 11;
    int h    = bh & (N_HEADS - 1);
    int b    = bh >> 4;

    size_t rowq = (size_t)(b * SEQ + i) * QKV_LD + h * HEAD_DIM;
    q_s[w][lane]      = QKV[rowq + lane];
    q_s[w][lane + 32] = QKV[rowq + lane + 32];
    __syncwarp();

    int lb   = i & ~(BLK - 1);
    int nloc = (i & (BLK - 1)) + 1;
    int nsum = i >> 4;
    int nk   = nloc + nsum;

    float sc[5];
    float mymax = -1e30f;
    #pragma unroll
    for (int c = 0; c < 5; c++) {
        int t = lane + c * 32;
        if (t < nk) {
            int j = (t < nloc) ? (lb + t) : (((t - nloc) << 4) + 15);
            const float4* kp = reinterpret_cast<const float4*>(
                QKV + (size_t)(b * SEQ + j) * QKV_LD + D_MODEL + h * HEAD_DIM);
            float dot = 0.f;
            #pragma unroll
            for (int d = 0; d < 16; d++) {
                float4 kv = kp[d];
                dot = fmaf(kv.x, q_s[w][d * 4 + 0], dot);
                dot = fmaf(kv.y, q_s[w][d * 4 + 1], dot);
                dot = fmaf(kv.z, q_s[w][d * 4 + 2], dot);
                dot = fmaf(kv.w, q_s[w][d * 4 + 3], dot);
            }
            sc[c] = dot * 0.125f;
            mymax = fmaxf(mymax, sc[c]);
        }
    }
    #pragma unroll
    for (int o = 16; o; o >>= 1)
        mymax = fmaxf(mymax, __shfl_xor_sync(0xFFFFFFFFu, mymax, o));

    float mysum = 0.f;
    #pragma unroll
    for (int c = 0; c < 5; c++) {
        int t = lane + c * 32;
        if (t < nk) { sc[c] = __expf(sc[c] - mymax); mysum += sc[c]; }
    }
    #pragma unroll
    for (int o = 16; o; o >>= 1)
        mysum += __shfl_xor_sync(0xFFFFFFFFu, mysum, o);
    float inv = 1.f / mysum;

    #pragma unroll
    for (int c = 0; c < 5; c++) {
        int t = lane + c * 32;
        if (t < nk) p_s[w][t] = sc[c] * inv;
    }
    __syncwarp();

    float acc0 = 0.f, acc1 = 0.f;
    for (int t = 0; t < nk; t++) {
        int j = (t < nloc) ? (lb + t) : (((t - nloc) << 4) + 15);
        const float* vp = QKV + (size_t)(b * SEQ + j) * QKV_LD + 2 * D_MODEL + h * HEAD_DIM;
        float p = p_s[w][t];
        acc0 = fmaf(p, vp[lane],      acc0);
        acc1 = fmaf(p, vp[lane + 32], acc1);
    }
    size_t baseo = (size_t)(b * SEQ + i) * D_MODEL + h * HEAD_DIM;
    O[baseo + lane]      = rtf(acc0);
    O[baseo + lane + 32] = rtf(acc1);
}

// -------------------------------- launch ------------------------------------
static float* sym_addr(const void* sym) {
    void* p = nullptr;
    cudaGetSymbolAddress(&p, sym);
    return reinterpret_cast<float*>(p);
}

extern "C" void kernel_launch(void* const* d_in, const int* in_sizes, int n_in,
                              void* d_out, int out_size)
{
    const float* x     = (const float*)d_in[0];
    const float* ln1_g = (const float*)d_in[1];
    const float* ln1_b = (const float*)d_in[2];
    const float* wq    = (const float*)d_in[3];
    const float* bq    = (const float*)d_in[4];
    const float* wk    = (const float*)d_in[5];
    const float* bk    = (const float*)d_in[6];
    const float* wv    = (const float*)d_in[7];
    const float* bv    = (const float*)d_in[8];
    const float* wo    = (const float*)d_in[9];
    const float* bo    = (const float*)d_in[10];
    const float* ln2_g = (const float*)d_in[11];
    const float* ln2_b = (const float*)d_in[12];
    const float* w1    = (const float*)d_in[13];
    const float* b1    = (const float*)d_in[14];
    const float* w2    = (const float*)d_in[15];
    const float* b2    = (const float*)d_in[16];
    float* out = (float*)d_out;

    float* p_h    = sym_addr(g_h);
    float* p_qkv  = sym_addr(g_qkv);
    float* p_ctx  = sym_addr(g_ctx);
    float* p_x1   = sym_addr(g_x1);
    float* p_ff   = sym_addr(g_ff);
    float* p_wqkv = sym_addr(g_wqkv);
    float* p_bqkv = sym_addr(g_bqkv);
    float* p_wo   = sym_addr(g_wo_r);
    float* p_w1   = sym_addr(g_w1_r);
    float* p_w2   = sym_addr(g_w2_r);

    const int M = M_ROWS;
    constexpr int SMEM_BYTES =
        (3 * 128 * 36 + 3 * 32 * 136) * (int)sizeof(float);  // 107,520 B

    cudaFuncSetAttribute(tgemm_kernel<0>, cudaFuncAttributeMaxDynamicSharedMemorySize, SMEM_BYTES);
    cudaFuncSetAttribute(tgemm_kernel<1>, cudaFuncAttributeMaxDynamicSharedMemorySize, SMEM_BYTES);
    cudaFuncSetAttribute(tgemm_kernel<2>, cudaFuncAttributeMaxDynamicSharedMemorySize, SMEM_BYTES);

    // ---- round + pack weights (every call; deterministic) ----
    round_pack_kernel<<<dim3(D_MODEL, 1), 256>>>(
        (const float4*)wq, (float4*)(p_wqkv + 0),            D_MODEL / 4, QKV_LD / 4);
    round_pack_kernel<<<dim3(D_MODEL, 1), 256>>>(
        (const float4*)wk, (float4*)(p_wqkv + D_MODEL),      D_MODEL / 4, QKV_LD / 4);
    round_pack_kernel<<<dim3(D_MODEL, 1), 256>>>(
        (const float4*)wv, (float4*)(p_wqkv + 2 * D_MODEL),  D_MODEL / 4, QKV_LD / 4);
    round_pack_kernel<<<dim3(D_MODEL, 1), 256>>>(
        (const float4*)wo, (float4*)p_wo, D_MODEL / 4, D_MODEL / 4);
    round_pack_kernel<<<dim3(D_MODEL, 4), 256>>>(
        (const float4*)w1, (float4*)p_w1, HIDDEN / 4, HIDDEN / 4);
    round_pack_kernel<<<dim3(HIDDEN, 1), 256>>>(
        (const float4*)w2, (float4*)p_w2, D_MODEL / 4, D_MODEL / 4);
    // biases: exact copy (added in fp32 epilogue)
    cudaMemcpyAsync(p_bqkv,               bq, D_MODEL * sizeof(float), cudaMemcpyDeviceToDevice, 0);
    cudaMemcpyAsync(p_bqkv + D_MODEL,     bk, D_MODEL * sizeof(float), cudaMemcpyDeviceToDevice, 0);
    cudaMemcpyAsync(p_bqkv + 2 * D_MODEL, bv, D_MODEL * sizeof(float), cudaMemcpyDeviceToDevice, 0);

    // ---- LN1 ----
    ln_kernel<<<M, 256>>>(x, ln1_g, ln1_b, p_h);

    // ---- fused QKV ----
    dim3 gQKV(QKV_LD / 128, M / 128);
    tgemm_kernel<0><<<gQKV, 128, SMEM_BYTES>>>(p_h, p_wqkv, p_bqkv, nullptr,
                                               p_qkv, M, QKV_LD, D_MODEL);

    // ---- sparse attention ----
    sparse_attn_kernel<<<(BATCH * N_HEADS * SEQ) / 4, 128>>>(p_qkv, p_ctx);

    // ---- Wo + residual ----
    dim3 gD(D_MODEL / 128, M / 128);
    tgemm_kernel<1><<<gD, 128, SMEM_BYTES>>>(p_ctx, p_wo, bo, x, p_x1,
                                             M, D_MODEL, D_MODEL);

    // ---- LN2 ----
    ln_kernel<<<M, 256>>>(p_x1, ln2_g, ln2_b, p_h);

    // ---- FFN ----
    dim3 gH(HIDDEN / 128, M / 128);
    tgemm_kernel<2><<<gH, 128, SMEM_BYTES>>>(p_h, p_w1, b1, nullptr, p_ff,
                                             M, HIDDEN, D_MODEL);
    tgemm_kernel<1><<<gD, 128, SMEM_BYTES>>>(p_ff, p_w2, b2, p_x1, out,
                                             M, D_MODEL, HIDDEN);
}